// round 2
// baseline (speedup 1.0000x reference)
#include <cuda_runtime.h>
#include <math.h>

// ---------------- problem constants ----------------
#define VOCAB     32000
#define N_TOKENS  16
#define TOK_DIM   64
#define NODE_DIM  64
#define HID       128
#define NG        1024
#define MAXN      100000
#define MAXE      1600000

// ---------------- scratch (static device globals; no allocation) ----------------
__device__ float g_embWp[VOCAB * NODE_DIM];   // emb @ Wp   (8.2 MB)
__device__ float g_node [MAXN * NODE_DIM];    // node features (25.6 MB)
__device__ float g_h    [MAXN * HID];         // x @ W (pre-aggregation) (51.2 MB)
__device__ float g_x    [MAXN * HID];         // aggregated / relu'd    (51.2 MB)
__device__ float g_dis  [MAXN];               // deg -> rsqrt(deg)
__device__ float g_gsum [NG * HID];
__device__ float g_gcnt [NG];

// ---------------- generic small GEMM: Y[N,M] = X[N,K] @ W[K,M] ----------------
// Block tile: 16 rows x M cols. blockDim.x = M. Each thread: 4 rows x 4 cols.
template<int K, int M>
__global__ void gemm_kernel(const float* __restrict__ X, const float* __restrict__ W,
                            float* __restrict__ Y, int N) {
    __shared__ float xs[K * 20];            // xs[k*20 + r], r in [0,16)
    const int row0 = blockIdx.x * 16;
    const int tid  = threadIdx.x;

    for (int idx = tid; idx < 16 * K; idx += blockDim.x) {
        int r = idx / K, k = idx - r * K;
        int row = row0 + r;
        xs[k * 20 + r] = (row < N) ? X[row * K + k] : 0.0f;
    }
    __syncthreads();

    const int ncg  = M / 4;
    const int colg = tid % ncg;
    const int rowg = tid / ncg;              // 0..3
    const int col0 = colg * 4;
    const int r0   = rowg * 4;

    float acc[4][4];
#pragma unroll
    for (int r = 0; r < 4; r++)
#pragma unroll
        for (int c = 0; c < 4; c++) acc[r][c] = 0.0f;

#pragma unroll 4
    for (int k = 0; k < K; k++) {
        float4 xv = *(const float4*)(xs + k * 20 + r0);
        float4 wv = *(const float4*)(W + k * M + col0);
        float xr[4] = {xv.x, xv.y, xv.z, xv.w};
        float wc[4] = {wv.x, wv.y, wv.z, wv.w};
#pragma unroll
        for (int r = 0; r < 4; r++)
#pragma unroll
            for (int c = 0; c < 4; c++) acc[r][c] += xr[r] * wc[c];
    }

#pragma unroll
    for (int r = 0; r < 4; r++) {
        int row = row0 + r0 + r;
        if (row < N) {
            float4 o = make_float4(acc[r][0], acc[r][1], acc[r][2], acc[r][3]);
            *(float4*)(Y + row * M + col0) = o;
        }
    }
}

// ---------------- token gather + mean pool (+bp): node = mean(embWp[tok]) + bp ----------------
// one warp per node, each lane owns 2 dims (float2)
__global__ void embed_pool_kernel(const int* __restrict__ tokens,
                                  const float* __restrict__ embWp,
                                  const float* __restrict__ bp,
                                  float* __restrict__ node, int N) {
    int warp = (blockIdx.x * blockDim.x + threadIdx.x) >> 5;
    int lane = threadIdx.x & 31;
    if (warp >= N) return;
    const int* tp = tokens + warp * N_TOKENS;
    float2 acc = make_float2(0.f, 0.f);
#pragma unroll
    for (int t = 0; t < N_TOKENS; t++) {
        int tok = tp[t];
        float2 v = ((const float2*)embWp)[tok * (NODE_DIM / 2) + lane];
        acc.x += v.x; acc.y += v.y;
    }
    float2 b = ((const float2*)bp)[lane];
    float2 o = make_float2(acc.x * (1.0f / N_TOKENS) + b.x,
                           acc.y * (1.0f / N_TOKENS) + b.y);
    ((float2*)node)[warp * (NODE_DIM / 2) + lane] = o;
}

// ---------------- degree / normalization ----------------
__global__ void deg_init_kernel(float* __restrict__ deg, int N) {
    int i = blockIdx.x * blockDim.x + threadIdx.x;
    if (i < N) deg[i] = 1.0f;   // self loop
}
__global__ void deg_edge_kernel(const int* __restrict__ dst, float* __restrict__ deg, int E) {
    int e = blockIdx.x * blockDim.x + threadIdx.x;
    if (e < E) atomicAdd(deg + dst[e], 1.0f);
}
__global__ void dis_kernel(float* __restrict__ dis, int N) {
    int i = blockIdx.x * blockDim.x + threadIdx.x;
    if (i < N) dis[i] = rsqrtf(dis[i]);
}

// ---------------- self-loop init: out[i] = h[i] * dis[i]^2 ----------------
__global__ void selfloop_kernel(const float* __restrict__ h, const float* __restrict__ dis,
                                float* __restrict__ out, int N) {
    int i = blockIdx.x * blockDim.x + threadIdx.x;   // over N*(HID/4)
    if (i >= N * (HID / 4)) return;
    int row = i / (HID / 4);
    float d = dis[row];
    float w = d * d;
    float4 v = ((const float4*)h)[i];
    v.x *= w; v.y *= w; v.z *= w; v.w *= w;
    ((float4*)out)[i] = v;
}

// ---------------- edge aggregation: out[dst] += h[src]*dis[src]*dis[dst] ----------------
// one warp per edge, float4 per lane (128 cols), vectorized global reduction
__global__ void agg_edge_kernel(const int* __restrict__ src, const int* __restrict__ dst,
                                const float* __restrict__ dis, const float* __restrict__ h,
                                float* __restrict__ out, int E) {
    int e    = (blockIdx.x * blockDim.x + threadIdx.x) >> 5;
    int lane = threadIdx.x & 31;
    if (e >= E) return;
    int s = __ldg(src + e);
    int d = __ldg(dst + e);
    float w = __ldg(dis + s) * __ldg(dis + d);
    float4 v = ((const float4*)h)[s * (HID / 4) + lane];
    v.x *= w; v.y *= w; v.z *= w; v.w *= w;
    float* p = out + d * HID + lane * 4;
    asm volatile("red.global.add.v4.f32 [%0], {%1,%2,%3,%4};"
                 :: "l"(p), "f"(v.x), "f"(v.y), "f"(v.z), "f"(v.w) : "memory");
}

// ---------------- bias + relu (in place) ----------------
__global__ void bias_relu_kernel(float* __restrict__ x, const float* __restrict__ b, int N) {
    int i = blockIdx.x * blockDim.x + threadIdx.x;
    if (i >= N * HID) return;
    int c = i & (HID - 1);
    float v = x[i] + b[c];
    x[i] = v > 0.f ? v : 0.f;
}

// ---------------- graph pooling ----------------
__global__ void pool_zero_kernel() {
    int i = blockIdx.x * blockDim.x + threadIdx.x;
    if (i < NG * HID) g_gsum[i] = 0.f;
    if (i < NG)       g_gcnt[i] = 0.f;
}
__global__ void pool_node_kernel(const int* __restrict__ batch, const float* __restrict__ x, int N) {
    int n    = (blockIdx.x * blockDim.x + threadIdx.x) >> 5;
    int lane = threadIdx.x & 31;
    if (n >= N) return;
    int b = __ldg(batch + n);
    if (lane == 0) atomicAdd(g_gcnt + b, 1.0f);
    float4 v = ((const float4*)x)[n * (HID / 4) + lane];
    float* p = g_gsum + b * HID + lane * 4;
    asm volatile("red.global.add.v4.f32 [%0], {%1,%2,%3,%4};"
                 :: "l"(p), "f"(v.x), "f"(v.y), "f"(v.z), "f"(v.w) : "memory");
}

// ---------------- head: g=relu(mean@Wfc+bfc); logit=g@Wout+bout; out=[sigmoid, logits] ----------------
__global__ void head_kernel(const float* __restrict__ Wfc, const float* __restrict__ bfc,
                            const float* __restrict__ Wout, const float* __restrict__ bout,
                            float* __restrict__ out, int out_size) {
    __shared__ float gsh[HID];
    __shared__ float red[HID];
    int gid = blockIdx.x;
    int j   = threadIdx.x;   // 0..127
    float cnt = fmaxf(g_gcnt[gid], 1.0f);
    gsh[j] = g_gsum[gid * HID + j] / cnt;
    __syncthreads();
    float acc = bfc[j];
#pragma unroll 8
    for (int k = 0; k < HID; k++) acc += gsh[k] * Wfc[k * HID + j];
    acc = fmaxf(acc, 0.f);
    red[j] = acc * Wout[j];
    __syncthreads();
#pragma unroll
    for (int s = HID / 2; s > 0; s >>= 1) {
        if (j < s) red[j] += red[j + s];
        __syncthreads();
    }
    if (j == 0) {
        float logit = red[0] + bout[0];
        out[gid] = 1.0f / (1.0f + expf(-logit));
        if (out_size >= 2 * NG) out[NG + gid] = logit;
    }
}

// ---------------- launch ----------------
extern "C" void kernel_launch(void* const* d_in, const int* in_sizes, int n_in,
                              void* d_out, int out_size) {
    const int*   tokens = (const int*)  d_in[0];
    const int*   eidx   = (const int*)  d_in[1];
    const int*   batch  = (const int*)  d_in[2];
    const float* emb    = (const float*)d_in[3];
    const float* Wp     = (const float*)d_in[4];
    const float* bp     = (const float*)d_in[5];
    const float* W1     = (const float*)d_in[6];
    const float* b1     = (const float*)d_in[7];
    const float* W2     = (const float*)d_in[8];
    const float* b2     = (const float*)d_in[9];
    const float* Wfc    = (const float*)d_in[10];
    const float* bfc    = (const float*)d_in[11];
    const float* Wout   = (const float*)d_in[12];
    const float* bout   = (const float*)d_in[13];
    float* out = (float*)d_out;

    const int N = in_sizes[2];            // batch has N elements
    const int E = in_sizes[1] / 2;        // edge_index is [2, E]
    const int* src = eidx;
    const int* dst = eidx + E;

    float *embWp, *node, *h, *x, *dis;
    cudaGetSymbolAddress((void**)&embWp, g_embWp);
    cudaGetSymbolAddress((void**)&node,  g_node);
    cudaGetSymbolAddress((void**)&h,     g_h);
    cudaGetSymbolAddress((void**)&x,     g_x);
    cudaGetSymbolAddress((void**)&dis,   g_dis);

    // 1. embWp = emb @ Wp  [VOCAB, 64]
    gemm_kernel<TOK_DIM, NODE_DIM><<<(VOCAB + 15) / 16, NODE_DIM>>>(emb, Wp, embWp, VOCAB);

    // 2. node = mean(embWp[tokens]) + bp
    embed_pool_kernel<<<(N * 32 + 255) / 256, 256>>>(tokens, embWp, bp, node, N);

    // 3. degrees -> dis = rsqrt(deg)
    deg_init_kernel<<<(N + 255) / 256, 256>>>(dis, N);
    deg_edge_kernel<<<(E + 255) / 256, 256>>>(dst, dis, E);
    dis_kernel<<<(N + 255) / 256, 256>>>(dis, N);

    // ---- GCN layer 1 ----
    gemm_kernel<NODE_DIM, HID><<<(N + 15) / 16, HID>>>(node, W1, h, N);
    selfloop_kernel<<<(N * (HID / 4) + 255) / 256, 256>>>(h, dis, x, N);
    agg_edge_kernel<<<(E * 32 + 255) / 256, 256>>>(src, dst, dis, h, x, E);
    bias_relu_kernel<<<(N * HID + 255) / 256, 256>>>(x, b1, N);

    // ---- GCN layer 2 ----
    gemm_kernel<HID, HID><<<(N + 15) / 16, HID>>>(x, W2, h, N);
    selfloop_kernel<<<(N * (HID / 4) + 255) / 256, 256>>>(h, dis, x, N);
    agg_edge_kernel<<<(E * 32 + 255) / 256, 256>>>(src, dst, dis, h, x, E);
    bias_relu_kernel<<<(N * HID + 255) / 256, 256>>>(x, b2, N);

    // ---- global mean pool ----
    pool_zero_kernel<<<(NG * HID + 255) / 256, 256>>>();
    pool_node_kernel<<<(N * 32 + 255) / 256, 256>>>(batch, x, N);

    // ---- head ----
    head_kernel<<<NG, HID>>>(Wfc, bfc, Wout, bout, out, out_size);
}

// round 3
// speedup vs baseline: 1.3546x; 1.3546x over previous
#include <cuda_runtime.h>
#include <math.h>

// ---------------- problem constants ----------------
#define VOCAB     32000
#define N_TOKENS  16
#define TOK_DIM   64
#define NODE_DIM  64
#define HID       128
#define NG        1024
#define MAXN      100000
#define MAXE      1600000

// ---------------- scratch (static device globals; no allocation) ----------------
__device__ float g_embWp [VOCAB * NODE_DIM];   // emb @ Wp  (8.2 MB)
__device__ float g_node  [MAXN * NODE_DIM];    // pooled node features (25.6 MB)
__device__ float g_tmp   [MAXN * HID];         // aggregation output (51.2 MB)
__device__ float g_x     [MAXN * HID];         // layer output (51.2 MB)
__device__ float g_dis   [MAXN];               // rsqrt(deg)
__device__ int   g_ctr   [MAXN];               // histogram / scatter counters
__device__ int   g_rowptr[MAXN + 1];           // CSR row pointers (by dst)
__device__ uint2 g_csr   [MAXE];               // {src, weight} per edge, grouped by dst
__device__ float g_gsum  [NG * HID];
__device__ float g_gcnt  [NG];

// ---------------- GEMM: Y[N,M] = X[N,K] @ W[K,M]  (+ optional bias+relu epilogue) ----
// Block tile: 16 rows x M cols. blockDim.x = M. Each thread: 4 rows x 4 cols.
template<int K, int M, bool BIAS_RELU>
__global__ void gemm_kernel(const float* __restrict__ X, const float* __restrict__ W,
                            const float* __restrict__ bias,
                            float* __restrict__ Y, int N) {
    __shared__ float xs[K * 20];            // xs[k*20 + r], r in [0,16)
    const int row0 = blockIdx.x * 16;
    const int tid  = threadIdx.x;

    for (int idx = tid; idx < 16 * K; idx += blockDim.x) {
        int r = idx / K, k = idx - r * K;
        int row = row0 + r;
        xs[k * 20 + r] = (row < N) ? X[row * K + k] : 0.0f;
    }
    __syncthreads();

    const int ncg  = M / 4;
    const int colg = tid % ncg;
    const int rowg = tid / ncg;              // 0..3
    const int col0 = colg * 4;
    const int r0   = rowg * 4;

    float acc[4][4];
#pragma unroll
    for (int r = 0; r < 4; r++)
#pragma unroll
        for (int c = 0; c < 4; c++) acc[r][c] = 0.0f;

#pragma unroll 4
    for (int k = 0; k < K; k++) {
        float4 xv = *(const float4*)(xs + k * 20 + r0);
        float4 wv = *(const float4*)(W + k * M + col0);
        float xr[4] = {xv.x, xv.y, xv.z, xv.w};
        float wc[4] = {wv.x, wv.y, wv.z, wv.w};
#pragma unroll
        for (int r = 0; r < 4; r++)
#pragma unroll
            for (int c = 0; c < 4; c++) acc[r][c] += xr[r] * wc[c];
    }

    float4 bv = make_float4(0.f, 0.f, 0.f, 0.f);
    if (BIAS_RELU) bv = *(const float4*)(bias + col0);

#pragma unroll
    for (int r = 0; r < 4; r++) {
        int row = row0 + r0 + r;
        if (row < N) {
            float4 o;
            if (BIAS_RELU) {
                o = make_float4(fmaxf(acc[r][0] + bv.x, 0.f),
                                fmaxf(acc[r][1] + bv.y, 0.f),
                                fmaxf(acc[r][2] + bv.z, 0.f),
                                fmaxf(acc[r][3] + bv.w, 0.f));
            } else {
                o = make_float4(acc[r][0], acc[r][1], acc[r][2], acc[r][3]);
            }
            *(float4*)(Y + row * M + col0) = o;
        }
    }
}

// ---------------- token gather + mean pool (+bp): node = mean(embWp[tok]) + bp ----
__global__ void embed_pool_kernel(const int* __restrict__ tokens,
                                  const float* __restrict__ embWp,
                                  const float* __restrict__ bp,
                                  float* __restrict__ node, int N) {
    int warp = (blockIdx.x * blockDim.x + threadIdx.x) >> 5;
    int lane = threadIdx.x & 31;
    if (warp >= N) return;
    const int* tp = tokens + warp * N_TOKENS;
    float2 acc = make_float2(0.f, 0.f);
#pragma unroll
    for (int t = 0; t < N_TOKENS; t++) {
        int tok = tp[t];
        float2 v = ((const float2*)embWp)[tok * (NODE_DIM / 2) + lane];
        acc.x += v.x; acc.y += v.y;
    }
    float2 b = ((const float2*)bp)[lane];
    float2 o = make_float2(acc.x * (1.0f / N_TOKENS) + b.x,
                           acc.y * (1.0f / N_TOKENS) + b.y);
    ((float2*)node)[warp * (NODE_DIM / 2) + lane] = o;
}

// ---------------- CSR build ----------------
__global__ void hist_kernel(const int* __restrict__ dst, int* __restrict__ ctr, int E) {
    int e = blockIdx.x * blockDim.x + threadIdx.x;
    if (e < E) atomicAdd(ctr + dst[e], 1);
}

// single-block exclusive scan over deg counts; also computes dis = rsqrt(deg+1)
__global__ void scan_kernel(const int* __restrict__ deg, int* __restrict__ row_ptr,
                            float* __restrict__ dis, int N) {
    __shared__ int ssum[1024];
    int t = threadIdx.x;
    int chunk = (N + 1023) / 1024;
    int lo = t * chunk;
    int hi = lo + chunk; if (hi > N) hi = N; if (lo > N) lo = N;
    int s = 0;
    for (int i = lo; i < hi; i++) s += deg[i];
    ssum[t] = s;
    __syncthreads();
    // inclusive Hillis-Steele scan
    for (int off = 1; off < 1024; off <<= 1) {
        int v = (t >= off) ? ssum[t - off] : 0;
        __syncthreads();
        ssum[t] += v;
        __syncthreads();
    }
    int prefix = (t == 0) ? 0 : ssum[t - 1];
    for (int i = lo; i < hi; i++) {
        int d = deg[i];
        row_ptr[i] = prefix;
        dis[i] = rsqrtf((float)(d + 1));   // +1 self loop
        prefix += d;
    }
    if (t == 1023) row_ptr[N] = prefix;
}

__global__ void scatter_kernel(const int* __restrict__ src, const int* __restrict__ dst,
                               const int* __restrict__ row_ptr, const float* __restrict__ dis,
                               int* __restrict__ ctr, uint2* __restrict__ csr, int E) {
    int e = blockIdx.x * blockDim.x + threadIdx.x;
    if (e >= E) return;
    int s = __ldg(src + e), d = __ldg(dst + e);
    int off = atomicAdd(ctr + d, 1);
    float w = __ldg(dis + s) * __ldg(dis + d);
    csr[__ldg(row_ptr + d) + off] = make_uint2((unsigned)s, __float_as_uint(w));
}

// ---------------- CSR aggregation: out[i] = x[i]*dis[i]^2 + sum_j x[src_j]*w_j ----
__global__ void agg64_kernel(const int* __restrict__ row_ptr, const uint2* __restrict__ csr,
                             const float* __restrict__ dis, const float* __restrict__ xin,
                             float* __restrict__ xout, int N) {
    int node = (blockIdx.x * blockDim.x + threadIdx.x) >> 5;
    int lane = threadIdx.x & 31;
    if (node >= N) return;
    int beg = __ldg(row_ptr + node), end = __ldg(row_ptr + node + 1);
    float di = __ldg(dis + node);
    float w0 = di * di;
    float2 v = ((const float2*)xin)[node * 32 + lane];
    float2 acc = make_float2(v.x * w0, v.y * w0);
#pragma unroll 4
    for (int j = beg; j < end; j++) {
        uint2 e = __ldg(csr + j);
        int s = (int)e.x;
        float w = __uint_as_float(e.y);
        float2 u = ((const float2*)xin)[s * 32 + lane];
        acc.x += u.x * w; acc.y += u.y * w;
    }
    ((float2*)xout)[node * 32 + lane] = acc;
}

__global__ void agg128_kernel(const int* __restrict__ row_ptr, const uint2* __restrict__ csr,
                              const float* __restrict__ dis, const float* __restrict__ xin,
                              float* __restrict__ xout, int N) {
    int node = (blockIdx.x * blockDim.x + threadIdx.x) >> 5;
    int lane = threadIdx.x & 31;
    if (node >= N) return;
    int beg = __ldg(row_ptr + node), end = __ldg(row_ptr + node + 1);
    float di = __ldg(dis + node);
    float w0 = di * di;
    float4 v = ((const float4*)xin)[node * 32 + lane];
    float4 acc = make_float4(v.x * w0, v.y * w0, v.z * w0, v.w * w0);
#pragma unroll 4
    for (int j = beg; j < end; j++) {
        uint2 e = __ldg(csr + j);
        int s = (int)e.x;
        float w = __uint_as_float(e.y);
        float4 u = ((const float4*)xin)[s * 32 + lane];
        acc.x += u.x * w; acc.y += u.y * w; acc.z += u.z * w; acc.w += u.w * w;
    }
    ((float4*)xout)[node * 32 + lane] = acc;
}

// ---------------- graph pooling ----------------
__global__ void pool_node_kernel(const int* __restrict__ batch, const float* __restrict__ x, int N) {
    int n    = (blockIdx.x * blockDim.x + threadIdx.x) >> 5;
    int lane = threadIdx.x & 31;
    if (n >= N) return;
    int b = __ldg(batch + n);
    if (lane == 0) atomicAdd(g_gcnt + b, 1.0f);
    float4 v = ((const float4*)x)[n * (HID / 4) + lane];
    float* p = g_gsum + b * HID + lane * 4;
    asm volatile("red.global.add.v4.f32 [%0], {%1,%2,%3,%4};"
                 :: "l"(p), "f"(v.x), "f"(v.y), "f"(v.z), "f"(v.w) : "memory");
}

// ---------------- head ----------------
__global__ void head_kernel(const float* __restrict__ Wfc, const float* __restrict__ bfc,
                            const float* __restrict__ Wout, const float* __restrict__ bout,
                            float* __restrict__ out, int out_size) {
    __shared__ float gsh[HID];
    __shared__ float red[HID];
    int gid = blockIdx.x;
    int j   = threadIdx.x;   // 0..127
    float cnt = fmaxf(g_gcnt[gid], 1.0f);
    gsh[j] = g_gsum[gid * HID + j] / cnt;
    __syncthreads();
    float acc = bfc[j];
#pragma unroll 8
    for (int k = 0; k < HID; k++) acc += gsh[k] * Wfc[k * HID + j];
    acc = fmaxf(acc, 0.f);
    red[j] = acc * Wout[j];
    __syncthreads();
#pragma unroll
    for (int s = HID / 2; s > 0; s >>= 1) {
        if (j < s) red[j] += red[j + s];
        __syncthreads();
    }
    if (j == 0) {
        float logit = red[0] + bout[0];
        out[gid] = 1.0f / (1.0f + expf(-logit));
        if (out_size >= 2 * NG) out[NG + gid] = logit;
    }
}

// ---------------- launch ----------------
extern "C" void kernel_launch(void* const* d_in, const int* in_sizes, int n_in,
                              void* d_out, int out_size) {
    const int*   tokens = (const int*)  d_in[0];
    const int*   eidx   = (const int*)  d_in[1];
    const int*   batch  = (const int*)  d_in[2];
    const float* emb    = (const float*)d_in[3];
    const float* Wp     = (const float*)d_in[4];
    const float* bp     = (const float*)d_in[5];
    const float* W1     = (const float*)d_in[6];
    const float* b1     = (const float*)d_in[7];
    const float* W2     = (const float*)d_in[8];
    const float* b2     = (const float*)d_in[9];
    const float* Wfc    = (const float*)d_in[10];
    const float* bfc    = (const float*)d_in[11];
    const float* Wout   = (const float*)d_in[12];
    const float* bout   = (const float*)d_in[13];
    float* out = (float*)d_out;

    const int N = in_sizes[2];            // batch has N elements
    const int E = in_sizes[1] / 2;        // edge_index is [2, E]
    const int* src = eidx;
    const int* dst = eidx + E;

    float *embWp, *node, *tmp, *x, *dis, *gsum, *gcnt;
    int *ctr, *rowptr; uint2 *csr;
    cudaGetSymbolAddress((void**)&embWp,  g_embWp);
    cudaGetSymbolAddress((void**)&node,   g_node);
    cudaGetSymbolAddress((void**)&tmp,    g_tmp);
    cudaGetSymbolAddress((void**)&x,      g_x);
    cudaGetSymbolAddress((void**)&dis,    g_dis);
    cudaGetSymbolAddress((void**)&ctr,    g_ctr);
    cudaGetSymbolAddress((void**)&rowptr, g_rowptr);
    cudaGetSymbolAddress((void**)&csr,    g_csr);
    cudaGetSymbolAddress((void**)&gsum,   g_gsum);
    cudaGetSymbolAddress((void**)&gcnt,   g_gcnt);

    // --- CSR build (independent of features) ---
    cudaMemsetAsync(ctr, 0, N * sizeof(int));
    hist_kernel<<<(E + 255) / 256, 256>>>(dst, ctr, E);
    scan_kernel<<<1, 1024>>>(ctr, rowptr, dis, N);
    cudaMemsetAsync(ctr, 0, N * sizeof(int));
    scatter_kernel<<<(E + 255) / 256, 256>>>(src, dst, rowptr, dis, ctr, csr, E);

    // --- features: embWp = emb @ Wp; node = mean(embWp[tokens]) + bp ---
    gemm_kernel<TOK_DIM, NODE_DIM, false><<<(VOCAB + 15) / 16, NODE_DIM>>>(emb, Wp, nullptr, embWp, VOCAB);
    embed_pool_kernel<<<(N * 32 + 255) / 256, 256>>>(tokens, embWp, bp, node, N);

    // ---- GCN layer 1 (aggregate 64-dim, then transform+bias+relu) ----
    agg64_kernel<<<(N * 32 + 255) / 256, 256>>>(rowptr, csr, dis, node, tmp, N);
    gemm_kernel<NODE_DIM, HID, true><<<(N + 15) / 16, HID>>>(tmp, W1, b1, x, N);

    // ---- GCN layer 2 ----
    agg128_kernel<<<(N * 32 + 255) / 256, 256>>>(rowptr, csr, dis, x, tmp, N);
    gemm_kernel<HID, HID, true><<<(N + 15) / 16, HID>>>(tmp, W2, b2, x, N);

    // ---- global mean pool ----
    cudaMemsetAsync(gsum, 0, NG * HID * sizeof(float));
    cudaMemsetAsync(gcnt, 0, NG * sizeof(float));
    pool_node_kernel<<<(N * 32 + 255) / 256, 256>>>(batch, x, N);

    // ---- head ----
    head_kernel<<<NG, HID>>>(Wfc, bfc, Wout, bout, out, out_size);
}

// round 5
// speedup vs baseline: 1.5351x; 1.1332x over previous
#include <cuda_runtime.h>
#include <cuda_bf16.h>
#include <math.h>
#include <stdint.h>

// ---------------- problem constants ----------------
#define VOCAB     32000
#define N_TOKENS  16
#define TOK_DIM   64
#define NODE_DIM  64
#define HID       128
#define NG        1024
#define MAXN      100000
#define MAXE      1600000

// ---------------- scratch (static device globals; no allocation) ----------------
__device__ float g_embWp [VOCAB * NODE_DIM];
__device__ float g_node  [MAXN * NODE_DIM];
__device__ float g_tmp   [MAXN * HID];
__device__ float g_x     [MAXN * HID];
__device__ float g_dis   [MAXN];
__device__ int   g_ctr   [MAXN];
__device__ int   g_rowptr[MAXN + 1];
__device__ uint2 g_csr   [MAXE];
__device__ float g_gsum  [NG * HID];
__device__ float g_gcnt  [NG];
__device__ __nv_bfloat16 g_wpth[NODE_DIM * TOK_DIM];  // Wp^T hi [64][64]
__device__ __nv_bfloat16 g_wptl[NODE_DIM * TOK_DIM];
__device__ __nv_bfloat16 g_wt1h[HID * NODE_DIM];      // W1^T hi [128][64]
__device__ __nv_bfloat16 g_wt1l[HID * NODE_DIM];
__device__ __nv_bfloat16 g_wt2h[HID * HID];           // W2^T hi [128][128]
__device__ __nv_bfloat16 g_wt2l[HID * HID];

// ================= mma helpers (sm_80-era PTX, valid on compute_103) =================
__device__ __forceinline__ uint32_t smem_u32(const void* p) {
    uint32_t a;
    asm("{ .reg .u64 t; cvta.to.shared.u64 t, %1; cvt.u32.u64 %0, t; }" : "=r"(a) : "l"(p));
    return a;
}
__device__ __forceinline__ void ldsm4(uint32_t (&r)[4], uint32_t addr) {
    asm volatile("ldmatrix.sync.aligned.m8n8.x4.shared.b16 {%0,%1,%2,%3}, [%4];"
                 : "=r"(r[0]), "=r"(r[1]), "=r"(r[2]), "=r"(r[3]) : "r"(addr));
}
__device__ __forceinline__ void mma16816(float (&d)[4], const uint32_t (&a)[4],
                                         uint32_t b0, uint32_t b1) {
    asm volatile("mma.sync.aligned.m16n8k16.row.col.f32.bf16.bf16.f32 "
                 "{%0,%1,%2,%3}, {%4,%5,%6,%7}, {%8,%9}, {%0,%1,%2,%3};"
                 : "+f"(d[0]), "+f"(d[1]), "+f"(d[2]), "+f"(d[3])
                 : "r"(a[0]), "r"(a[1]), "r"(a[2]), "r"(a[3]), "r"(b0), "r"(b1));
}

// ================= W^T split conversion: wt[n][k] = split_bf16(W[k][n]) =================
template<int K, int MOUT>
__global__ void convert_w_kernel(const float* __restrict__ W,
                                 __nv_bfloat16* __restrict__ hi,
                                 __nv_bfloat16* __restrict__ lo) {
    int i = blockIdx.x * blockDim.x + threadIdx.x;
    if (i >= MOUT * K) return;
    int n = i / K, k = i - n * K;
    float f = W[k * MOUT + n];
    __nv_bfloat16 h = __float2bfloat16(f);
    hi[i] = h;
    lo[i] = __float2bfloat16(f - __bfloat162float(h));
}

// ================= tensor-core GEMM: Y[N,MOUT] = (relu)(X[N,K] @ W (+b)) =================
// split-bf16: D = Ah*Bh + Ah*Bl + Al*Bh  (fp32 accumulate)
// 256 threads, tile 128 x MOUT, 8 warps as 4(m) x 2(n).
template<int K, int MOUT, bool BIAS_RELU>
__global__ __launch_bounds__(256) void mma_gemm_kernel(
    const float* __restrict__ X,
    const __nv_bfloat16* __restrict__ Wth, const __nv_bfloat16* __restrict__ Wtl,
    const float* __restrict__ bias, float* __restrict__ Y, int N) {
    extern __shared__ char smem[];
    constexpr int P    = K * 2 + 16;       // row pitch (bytes): 16B pad -> conflict-free ldmatrix
    constexpr int A_HI = 512;
    constexpr int A_LO = A_HI + 128 * P;
    constexpr int B_HI = A_LO + 128 * P;
    constexpr int B_LO = B_HI + MOUT * P;
    constexpr int NT   = MOUT / 16;        // 8-col n-tiles per warp
    constexpr int NT2  = NT / 2;
    constexpr int KS   = K / 16;
    constexpr int KQ   = K / 4;

    const int tid = threadIdx.x, wid = tid >> 5, lane = tid & 31;
    const int row0 = blockIdx.x * 128;
    float* bs = (float*)smem;
    if (BIAS_RELU && tid < MOUT) bs[tid] = bias[tid];

    // ---- fill A tiles: convert fp32 rows -> split bf16 ----
    for (int idx = tid; idx < 128 * KQ; idx += 256) {
        int r = idx / KQ, kq = idx - r * KQ;
        int row = row0 + r;
        float4 v = (row < N) ? *(const float4*)(X + (long)row * K + kq * 4)
                             : make_float4(0.f, 0.f, 0.f, 0.f);
        float f[4] = {v.x, v.y, v.z, v.w};
        __nv_bfloat16 h[4], l[4];
#pragma unroll
        for (int j = 0; j < 4; j++) {
            h[j] = __float2bfloat16(f[j]);
            l[j] = __float2bfloat16(f[j] - __bfloat162float(h[j]));
        }
        __nv_bfloat162 h01(h[0], h[1]), h23(h[2], h[3]);
        __nv_bfloat162 l01(l[0], l[1]), l23(l[2], l[3]);
        *(uint2*)(smem + A_HI + r * P + kq * 8) = make_uint2(*(uint32_t*)&h01, *(uint32_t*)&h23);
        *(uint2*)(smem + A_LO + r * P + kq * 8) = make_uint2(*(uint32_t*)&l01, *(uint32_t*)&l23);
    }
    // ---- fill B tiles: copy pre-split bf16 W^T [n][k] ----
    for (int idx = tid; idx < MOUT * KQ; idx += 256) {
        int r = idx / KQ, kq = idx - r * KQ;
        *(uint2*)(smem + B_HI + r * P + kq * 8) = *(const uint2*)(Wth + r * K + kq * 4);
        *(uint2*)(smem + B_LO + r * P + kq * 8) = *(const uint2*)(Wtl + r * K + kq * 4);
    }
    __syncthreads();

    const int wm = (wid >> 1) * 32;
    const int wn = (wid & 1) * (MOUT / 2);
    const int grp = lane >> 3, rr = lane & 7;
    const uint32_t sb = smem_u32(smem);
    // A x4 groups: (m0,k0),(m8,k0),(m0,k8),(m8,k8)
    const uint32_t aH = sb + A_HI + (uint32_t)(wm + (grp & 1) * 8 + rr) * P + ((grp >> 1) * 8) * 2;
    const uint32_t aL = aH + (uint32_t)(A_LO - A_HI);
    // B x4 groups: (n0,k0),(n0,k8),(n8,k0),(n8,k8)
    const uint32_t bH = sb + B_HI + (uint32_t)(wn + (grp >> 1) * 8 + rr) * P + ((grp & 1) * 8) * 2;
    const uint32_t bL = bH + (uint32_t)(B_LO - B_HI);

    float acc[2][NT][4];
#pragma unroll
    for (int mt = 0; mt < 2; mt++)
#pragma unroll
        for (int nt = 0; nt < NT; nt++)
#pragma unroll
            for (int j = 0; j < 4; j++) acc[mt][nt][j] = 0.f;

#pragma unroll
    for (int ks = 0; ks < KS; ks++) {
        uint32_t ah[2][4], al[2][4], bh[NT2][4], bl[NT2][4];
#pragma unroll
        for (int mt = 0; mt < 2; mt++) {
            ldsm4(ah[mt], aH + mt * 16 * P + ks * 32);
            ldsm4(al[mt], aL + mt * 16 * P + ks * 32);
        }
#pragma unroll
        for (int nt2 = 0; nt2 < NT2; nt2++) {
            ldsm4(bh[nt2], bH + nt2 * 16 * P + ks * 32);
            ldsm4(bl[nt2], bL + nt2 * 16 * P + ks * 32);
        }
#pragma unroll
        for (int mt = 0; mt < 2; mt++)
#pragma unroll
            for (int nt2 = 0; nt2 < NT2; nt2++)
#pragma unroll
                for (int h = 0; h < 2; h++) {
                    float (&d)[4] = acc[mt][nt2 * 2 + h];
                    mma16816(d, ah[mt], bh[nt2][h * 2], bh[nt2][h * 2 + 1]);
                    mma16816(d, ah[mt], bl[nt2][h * 2], bl[nt2][h * 2 + 1]);
                    mma16816(d, al[mt], bh[nt2][h * 2], bh[nt2][h * 2 + 1]);
                }
    }

    // ---- epilogue: (bias+relu) + store ----
    const int lrow = lane >> 2;
    const int lcol = (lane & 3) * 2;
#pragma unroll
    for (int mt = 0; mt < 2; mt++) {
        int row = row0 + wm + mt * 16 + lrow;
#pragma unroll
        for (int nt = 0; nt < NT; nt++) {
            int col = wn + nt * 8 + lcol;
            float2 v0 = make_float2(acc[mt][nt][0], acc[mt][nt][1]);
            float2 v1 = make_float2(acc[mt][nt][2], acc[mt][nt][3]);
            if (BIAS_RELU) {
                float b0 = bs[col], b1 = bs[col + 1];
                v0.x = fmaxf(v0.x + b0, 0.f); v0.y = fmaxf(v0.y + b1, 0.f);
                v1.x = fmaxf(v1.x + b0, 0.f); v1.y = fmaxf(v1.y + b1, 0.f);
            }
            if (row < N)     *(float2*)(Y + (long)row * MOUT + col)       = v0;
            if (row + 8 < N) *(float2*)(Y + (long)(row + 8) * MOUT + col) = v1;
        }
    }
}

// ================= token gather + mean pool =================
__global__ void embed_pool_kernel(const int* __restrict__ tokens,
                                  const float* __restrict__ embWp,
                                  const float* __restrict__ bp,
                                  float* __restrict__ node, int N) {
    int warp = (blockIdx.x * blockDim.x + threadIdx.x) >> 5;
    int lane = threadIdx.x & 31;
    if (warp >= N) return;
    const int* tp = tokens + warp * N_TOKENS;
    float2 acc = make_float2(0.f, 0.f);
#pragma unroll
    for (int t = 0; t < N_TOKENS; t++) {
        int tok = tp[t];
        float2 v = ((const float2*)embWp)[tok * (NODE_DIM / 2) + lane];
        acc.x += v.x; acc.y += v.y;
    }
    float2 b = ((const float2*)bp)[lane];
    float2 o = make_float2(acc.x * (1.0f / N_TOKENS) + b.x,
                           acc.y * (1.0f / N_TOKENS) + b.y);
    ((float2*)node)[warp * (NODE_DIM / 2) + lane] = o;
}

// ================= CSR build =================
__global__ void hist_kernel(const int* __restrict__ dst, int* __restrict__ ctr, int E) {
    int e = blockIdx.x * blockDim.x + threadIdx.x;
    if (e < E) atomicAdd(ctr + dst[e], 1);
}
__global__ void scan_kernel(const int* __restrict__ deg, int* __restrict__ row_ptr,
                            float* __restrict__ dis, int N) {
    __shared__ int ssum[1024];
    int t = threadIdx.x;
    int chunk = (N + 1023) / 1024;
    int lo = t * chunk;
    int hi = lo + chunk; if (hi > N) hi = N; if (lo > N) lo = N;
    int s = 0;
    for (int i = lo; i < hi; i++) s += deg[i];
    ssum[t] = s;
    __syncthreads();
    for (int off = 1; off < 1024; off <<= 1) {
        int v = (t >= off) ? ssum[t - off] : 0;
        __syncthreads();
        ssum[t] += v;
        __syncthreads();
    }
    int prefix = (t == 0) ? 0 : ssum[t - 1];
    for (int i = lo; i < hi; i++) {
        int d = deg[i];
        row_ptr[i] = prefix;
        dis[i] = rsqrtf((float)(d + 1));
        prefix += d;
    }
    if (t == 1023) row_ptr[N] = prefix;
}
__global__ void scatter_kernel(const int* __restrict__ src, const int* __restrict__ dst,
                               const int* __restrict__ row_ptr, const float* __restrict__ dis,
                               int* __restrict__ ctr, uint2* __restrict__ csr, int E) {
    int e = blockIdx.x * blockDim.x + threadIdx.x;
    if (e >= E) return;
    int s = __ldg(src + e), d = __ldg(dst + e);
    int off = atomicAdd(ctr + d, 1);
    float w = __ldg(dis + s) * __ldg(dis + d);
    csr[__ldg(row_ptr + d) + off] = make_uint2((unsigned)s, __float_as_uint(w));
}

// ================= CSR aggregation =================
__global__ void agg64_kernel(const int* __restrict__ row_ptr, const uint2* __restrict__ csr,
                             const float* __restrict__ dis, const float* __restrict__ xin,
                             float* __restrict__ xout, int N) {
    int node = (blockIdx.x * blockDim.x + threadIdx.x) >> 5;
    int lane = threadIdx.x & 31;
    if (node >= N) return;
    int beg = __ldg(row_ptr + node), end = __ldg(row_ptr + node + 1);
    float di = __ldg(dis + node);
    float w0 = di * di;
    float2 v = ((const float2*)xin)[node * 32 + lane];
    float2 acc = make_float2(v.x * w0, v.y * w0);
#pragma unroll 4
    for (int j = beg; j < end; j++) {
        uint2 e = __ldg(csr + j);
        int s = (int)e.x;
        float w = __uint_as_float(e.y);
        float2 u = ((const float2*)xin)[s * 32 + lane];
        acc.x += u.x * w; acc.y += u.y * w;
    }
    ((float2*)xout)[node * 32 + lane] = acc;
}
__global__ void agg128_kernel(const int* __restrict__ row_ptr, const uint2* __restrict__ csr,
                              const float* __restrict__ dis, const float* __restrict__ xin,
                              float* __restrict__ xout, int N) {
    int node = (blockIdx.x * blockDim.x + threadIdx.x) >> 5;
    int lane = threadIdx.x & 31;
    if (node >= N) return;
    int beg = __ldg(row_ptr + node), end = __ldg(row_ptr + node + 1);
    float di = __ldg(dis + node);
    float w0 = di * di;
    float4 v = ((const float4*)xin)[node * 32 + lane];
    float4 acc = make_float4(v.x * w0, v.y * w0, v.z * w0, v.w * w0);
#pragma unroll 4
    for (int j = beg; j < end; j++) {
        uint2 e = __ldg(csr + j);
        int s = (int)e.x;
        float w = __uint_as_float(e.y);
        float4 u = ((const float4*)xin)[s * 32 + lane];
        acc.x += u.x * w; acc.y += u.y * w; acc.z += u.z * w; acc.w += u.w * w;
    }
    ((float4*)xout)[node * 32 + lane] = acc;
}

// ================= graph pooling =================
__global__ void pool_node_kernel(const int* __restrict__ batch, const float* __restrict__ x, int N) {
    int n    = (blockIdx.x * blockDim.x + threadIdx.x) >> 5;
    int lane = threadIdx.x & 31;
    if (n >= N) return;
    int b = __ldg(batch + n);
    if (lane == 0) atomicAdd(g_gcnt + b, 1.0f);
    float4 v = ((const float4*)x)[n * (HID / 4) + lane];
    float* p = g_gsum + b * HID + lane * 4;
    asm volatile("red.global.add.v4.f32 [%0], {%1,%2,%3,%4};"
                 :: "l"(p), "f"(v.x), "f"(v.y), "f"(v.z), "f"(v.w) : "memory");
}

// ================= head =================
__global__ void head_kernel(const float* __restrict__ Wfc, const float* __restrict__ bfc,
                            const float* __restrict__ Wout, const float* __restrict__ bout,
                            float* __restrict__ out, int out_size) {
    __shared__ float gsh[HID];
    __shared__ float red[HID];
    int gid = blockIdx.x;
    int j   = threadIdx.x;
    float cnt = fmaxf(g_gcnt[gid], 1.0f);
    gsh[j] = g_gsum[gid * HID + j] / cnt;
    __syncthreads();
    float acc = bfc[j];
#pragma unroll 8
    for (int k = 0; k < HID; k++) acc += gsh[k] * Wfc[k * HID + j];
    acc = fmaxf(acc, 0.f);
    red[j] = acc * Wout[j];
    __syncthreads();
#pragma unroll
    for (int s = HID / 2; s > 0; s >>= 1) {
        if (j < s) red[j] += red[j + s];
        __syncthreads();
    }
    if (j == 0) {
        float logit = red[0] + bout[0];
        out[gid] = 1.0f / (1.0f + expf(-logit));
        if (out_size >= 2 * NG) out[NG + gid] = logit;
    }
}

// ================= launch =================
extern "C" void kernel_launch(void* const* d_in, const int* in_sizes, int n_in,
                              void* d_out, int out_size) {
    const int*   tokens = (const int*)  d_in[0];
    const int*   eidx   = (const int*)  d_in[1];
    const int*   batch  = (const int*)  d_in[2];
    const float* emb    = (const float*)d_in[3];
    const float* Wp     = (const float*)d_in[4];
    const float* bp     = (const float*)d_in[5];
    const float* W1     = (const float*)d_in[6];
    const float* b1     = (const float*)d_in[7];
    const float* W2     = (const float*)d_in[8];
    const float* b2     = (const float*)d_in[9];
    const float* Wfc    = (const float*)d_in[10];
    const float* bfc    = (const float*)d_in[11];
    const float* Wout   = (const float*)d_in[12];
    const float* bout   = (const float*)d_in[13];
    float* out = (float*)d_out;

    const int N = in_sizes[2];
    const int E = in_sizes[1] / 2;
    const int* src = eidx;
    const int* dst = eidx + E;

    float *embWp, *node, *tmp, *x, *dis, *gsum, *gcnt;
    int *ctr, *rowptr; uint2 *csr;
    __nv_bfloat16 *wpth, *wptl, *wt1h, *wt1l, *wt2h, *wt2l;
    cudaGetSymbolAddress((void**)&embWp,  g_embWp);
    cudaGetSymbolAddress((void**)&node,   g_node);
    cudaGetSymbolAddress((void**)&tmp,    g_tmp);
    cudaGetSymbolAddress((void**)&x,      g_x);
    cudaGetSymbolAddress((void**)&dis,    g_dis);
    cudaGetSymbolAddress((void**)&ctr,    g_ctr);
    cudaGetSymbolAddress((void**)&rowptr, g_rowptr);
    cudaGetSymbolAddress((void**)&csr,    g_csr);
    cudaGetSymbolAddress((void**)&gsum,   g_gsum);
    cudaGetSymbolAddress((void**)&gcnt,   g_gcnt);
    cudaGetSymbolAddress((void**)&wpth,   g_wpth);
    cudaGetSymbolAddress((void**)&wptl,   g_wptl);
    cudaGetSymbolAddress((void**)&wt1h,   g_wt1h);
    cudaGetSymbolAddress((void**)&wt1l,   g_wt1l);
    cudaGetSymbolAddress((void**)&wt2h,   g_wt2h);
    cudaGetSymbolAddress((void**)&wt2l,   g_wt2l);

    // dynamic smem sizes: 512 + 256*P + 2*MOUT*P, P = 2K+16
    const int SMEM_V  = 512 + 256 * 144 + 2 * 64  * 144;   //  55808 (K=64,  M=64)
    const int SMEM_L1 = 512 + 256 * 144 + 2 * 128 * 144;   //  74240 (K=64,  M=128)
    const int SMEM_L2 = 512 + 256 * 272 + 2 * 128 * 272;   // 139776 (K=128, M=128)
    cudaFuncSetAttribute(mma_gemm_kernel<64, 64, false>,  cudaFuncAttributeMaxDynamicSharedMemorySize, SMEM_V);
    cudaFuncSetAttribute(mma_gemm_kernel<64, 128, true>,  cudaFuncAttributeMaxDynamicSharedMemorySize, SMEM_L1);
    cudaFuncSetAttribute(mma_gemm_kernel<128, 128, true>, cudaFuncAttributeMaxDynamicSharedMemorySize, SMEM_L2);

    // --- CSR build + weight split conversion (feature-independent) ---
    cudaMemsetAsync(ctr, 0, N * sizeof(int));
    hist_kernel<<<(E + 255) / 256, 256>>>(dst, ctr, E);
    scan_kernel<<<1, 1024>>>(ctr, rowptr, dis, N);
    cudaMemsetAsync(ctr, 0, N * sizeof(int));
    scatter_kernel<<<(E + 255) / 256, 256>>>(src, dst, rowptr, dis, ctr, csr, E);
    convert_w_kernel<TOK_DIM, NODE_DIM><<<(NODE_DIM * TOK_DIM + 255) / 256, 256>>>(Wp, wpth, wptl);
    convert_w_kernel<NODE_DIM, HID><<<(HID * NODE_DIM + 255) / 256, 256>>>(W1, wt1h, wt1l);
    convert_w_kernel<HID, HID><<<(HID * HID + 255) / 256, 256>>>(W2, wt2h, wt2l);

    // --- features: embWp = emb @ Wp (tensor cores); node = mean(embWp[tokens]) + bp ---
    mma_gemm_kernel<64, 64, false><<<(VOCAB + 127) / 128, 256, SMEM_V>>>(
        emb, wpth, wptl, nullptr, embWp, VOCAB);
    embed_pool_kernel<<<(N * 32 + 255) / 256, 256>>>(tokens, embWp, bp, node, N);

    // ---- GCN layer 1: aggregate(64) -> tensor GEMM 64->128 + bias + relu ----
    agg64_kernel<<<(N * 32 + 255) / 256, 256>>>(rowptr, csr, dis, node, tmp, N);
    mma_gemm_kernel<64, 128, true><<<(N + 127) / 128, 256, SMEM_L1>>>(tmp, wt1h, wt1l, b1, x, N);

    // ---- GCN layer 2: aggregate(128) -> tensor GEMM 128->128 + bias + relu ----
    agg128_kernel<<<(N * 32 + 255) / 256, 256>>>(rowptr, csr, dis, x, tmp, N);
    mma_gemm_kernel<128, 128, true><<<(N + 127) / 128, 256, SMEM_L2>>>(tmp, wt2h, wt2l, b2, x, N);

    // ---- global mean pool ----
    cudaMemsetAsync(gsum, 0, NG * HID * sizeof(float));
    cudaMemsetAsync(gcnt, 0, NG * sizeof(float));
    pool_node_kernel<<<(N * 32 + 255) / 256, 256>>>(batch, x, N);

    // ---- head ----
    head_kernel<<<NG, HID>>>(Wfc, bfc, Wout, bout, out, out_size);
}

// round 6
// speedup vs baseline: 1.5973x; 1.0405x over previous
#include <cuda_runtime.h>
#include <cuda_bf16.h>
#include <math.h>
#include <stdint.h>

// ---------------- problem constants ----------------
#define VOCAB     32000
#define N_TOKENS  16
#define TOK_DIM   64
#define NODE_DIM  64
#define HID       128
#define NG        1024
#define MAXN      100000
#define MAXE      1600000

// ---------------- scratch (static device globals; no allocation) ----------------
__device__ float g_embWp [VOCAB * NODE_DIM];
__device__ float g_node  [MAXN * NODE_DIM];
__device__ float g_tmp   [MAXN * HID];
__device__ float g_x     [MAXN * HID];
__device__ float g_dis   [MAXN];
__device__ int   g_ctr   [MAXN];
__device__ int   g_rowptr[MAXN + 1];
__device__ uint2 g_csr   [MAXE];
__device__ float g_gsum  [NG * HID];
__device__ float g_gcnt  [NG];
__device__ __nv_bfloat16 g_wpth[NODE_DIM * TOK_DIM];  // Wp^T hi [64][64]
__device__ __nv_bfloat16 g_wptl[NODE_DIM * TOK_DIM];
__device__ __nv_bfloat16 g_wt1h[HID * NODE_DIM];      // W1^T hi [128][64]
__device__ __nv_bfloat16 g_wt1l[HID * NODE_DIM];
__device__ __nv_bfloat16 g_wt2h[HID * HID];           // W2^T hi [128][128]
__device__ __nv_bfloat16 g_wt2l[HID * HID];

// ================= mma helpers (sm_80-era PTX, valid on compute_103) =================
__device__ __forceinline__ uint32_t smem_u32(const void* p) {
    uint32_t a;
    asm("{ .reg .u64 t; cvta.to.shared.u64 t, %1; cvt.u32.u64 %0, t; }" : "=r"(a) : "l"(p));
    return a;
}
__device__ __forceinline__ void ldsm4(uint32_t (&r)[4], uint32_t addr) {
    asm volatile("ldmatrix.sync.aligned.m8n8.x4.shared.b16 {%0,%1,%2,%3}, [%4];"
                 : "=r"(r[0]), "=r"(r[1]), "=r"(r[2]), "=r"(r[3]) : "r"(addr));
}
__device__ __forceinline__ void mma16816(float (&d)[4], const uint32_t (&a)[4],
                                         uint32_t b0, uint32_t b1) {
    asm volatile("mma.sync.aligned.m16n8k16.row.col.f32.bf16.bf16.f32 "
                 "{%0,%1,%2,%3}, {%4,%5,%6,%7}, {%8,%9}, {%0,%1,%2,%3};"
                 : "+f"(d[0]), "+f"(d[1]), "+f"(d[2]), "+f"(d[3])
                 : "r"(a[0]), "r"(a[1]), "r"(a[2]), "r"(a[3]), "r"(b0), "r"(b1));
}

// ================= W^T split conversion: wt[n][k] = split_bf16(W[k][n]) =================
template<int K, int MOUT>
__global__ void convert_w_kernel(const float* __restrict__ W,
                                 __nv_bfloat16* __restrict__ hi,
                                 __nv_bfloat16* __restrict__ lo) {
    int i = blockIdx.x * blockDim.x + threadIdx.x;
    if (i >= MOUT * K) return;
    int n = i / K, k = i - n * K;
    float f = W[k * MOUT + n];
    __nv_bfloat16 h = __float2bfloat16(f);
    hi[i] = h;
    lo[i] = __float2bfloat16(f - __bfloat162float(h));
}

// ================= tensor-core GEMM: Y[N,MOUT] = (relu)(X[N,K] @ W (+b)) =================
// split-bf16: D = Ah*Bh + Ah*Bl + Al*Bh  (fp32 accumulate)
// 256 threads, tile 128 x MOUT, 8 warps as 4(m) x 2(n).
// MODE: 0 = plain store, 1 = bias+relu store, 2 = bias+relu + pooled red into gsum[batch[row]]
template<int K, int MOUT, int MODE>
__global__ __launch_bounds__(256) void mma_gemm_kernel(
    const float* __restrict__ X,
    const __nv_bfloat16* __restrict__ Wth, const __nv_bfloat16* __restrict__ Wtl,
    const float* __restrict__ bias, float* __restrict__ Y,
    const int* __restrict__ batch, float* __restrict__ gsum, int N) {
    extern __shared__ char smem[];
    constexpr int P    = K * 2 + 16;       // row pitch (bytes): 16B pad -> conflict-free ldmatrix
    constexpr int A_HI = 512;
    constexpr int A_LO = A_HI + 128 * P;
    constexpr int B_HI = A_LO + 128 * P;
    constexpr int B_LO = B_HI + MOUT * P;
    constexpr int NT   = MOUT / 16;        // 8-col n-tiles per warp
    constexpr int NT2  = NT / 2;
    constexpr int KS   = K / 16;
    constexpr int KQ   = K / 4;

    const int tid = threadIdx.x, wid = tid >> 5, lane = tid & 31;
    const int row0 = blockIdx.x * 128;
    float* bs = (float*)smem;
    if (MODE >= 1 && tid < MOUT) bs[tid] = bias[tid];

    // ---- fill A tiles: convert fp32 rows -> split bf16 ----
    for (int idx = tid; idx < 128 * KQ; idx += 256) {
        int r = idx / KQ, kq = idx - r * KQ;
        int row = row0 + r;
        float4 v = (row < N) ? *(const float4*)(X + (long)row * K + kq * 4)
                             : make_float4(0.f, 0.f, 0.f, 0.f);
        float f[4] = {v.x, v.y, v.z, v.w};
        __nv_bfloat16 h[4], l[4];
#pragma unroll
        for (int j = 0; j < 4; j++) {
            h[j] = __float2bfloat16(f[j]);
            l[j] = __float2bfloat16(f[j] - __bfloat162float(h[j]));
        }
        __nv_bfloat162 h01(h[0], h[1]), h23(h[2], h[3]);
        __nv_bfloat162 l01(l[0], l[1]), l23(l[2], l[3]);
        *(uint2*)(smem + A_HI + r * P + kq * 8) = make_uint2(*(uint32_t*)&h01, *(uint32_t*)&h23);
        *(uint2*)(smem + A_LO + r * P + kq * 8) = make_uint2(*(uint32_t*)&l01, *(uint32_t*)&l23);
    }
    // ---- fill B tiles: copy pre-split bf16 W^T [n][k] ----
    for (int idx = tid; idx < MOUT * KQ; idx += 256) {
        int r = idx / KQ, kq = idx - r * KQ;
        *(uint2*)(smem + B_HI + r * P + kq * 8) = *(const uint2*)(Wth + r * K + kq * 4);
        *(uint2*)(smem + B_LO + r * P + kq * 8) = *(const uint2*)(Wtl + r * K + kq * 4);
    }
    __syncthreads();

    const int wm = (wid >> 1) * 32;
    const int wn = (wid & 1) * (MOUT / 2);
    const int grp = lane >> 3, rr = lane & 7;
    const uint32_t sb = smem_u32(smem);
    const uint32_t aH = sb + A_HI + (uint32_t)(wm + (grp & 1) * 8 + rr) * P + ((grp >> 1) * 8) * 2;
    const uint32_t aL = aH + (uint32_t)(A_LO - A_HI);
    const uint32_t bH = sb + B_HI + (uint32_t)(wn + (grp >> 1) * 8 + rr) * P + ((grp & 1) * 8) * 2;
    const uint32_t bL = bH + (uint32_t)(B_LO - B_HI);

    float acc[2][NT][4];
#pragma unroll
    for (int mt = 0; mt < 2; mt++)
#pragma unroll
        for (int nt = 0; nt < NT; nt++)
#pragma unroll
            for (int j = 0; j < 4; j++) acc[mt][nt][j] = 0.f;

#pragma unroll
    for (int ks = 0; ks < KS; ks++) {
        uint32_t ah[2][4], al[2][4], bh[NT2][4], bl[NT2][4];
#pragma unroll
        for (int mt = 0; mt < 2; mt++) {
            ldsm4(ah[mt], aH + mt * 16 * P + ks * 32);
            ldsm4(al[mt], aL + mt * 16 * P + ks * 32);
        }
#pragma unroll
        for (int nt2 = 0; nt2 < NT2; nt2++) {
            ldsm4(bh[nt2], bH + nt2 * 16 * P + ks * 32);
            ldsm4(bl[nt2], bL + nt2 * 16 * P + ks * 32);
        }
#pragma unroll
        for (int mt = 0; mt < 2; mt++)
#pragma unroll
            for (int nt2 = 0; nt2 < NT2; nt2++)
#pragma unroll
                for (int h = 0; h < 2; h++) {
                    float (&d)[4] = acc[mt][nt2 * 2 + h];
                    mma16816(d, ah[mt], bh[nt2][h * 2], bh[nt2][h * 2 + 1]);
                    mma16816(d, ah[mt], bl[nt2][h * 2], bl[nt2][h * 2 + 1]);
                    mma16816(d, al[mt], bh[nt2][h * 2], bh[nt2][h * 2 + 1]);
                }
    }

    // ---- epilogue ----
    const int lrow = lane >> 2;
    const int lcol = (lane & 3) * 2;
#pragma unroll
    for (int mt = 0; mt < 2; mt++) {
        int row = row0 + wm + mt * 16 + lrow;
        int b0i = 0, b1i = 0;
        if (MODE == 2) {
            b0i = (row < N)     ? __ldg(batch + row)     : -1;
            b1i = (row + 8 < N) ? __ldg(batch + row + 8) : -1;
        }
#pragma unroll
        for (int nt = 0; nt < NT; nt++) {
            int col = wn + nt * 8 + lcol;
            float2 v0 = make_float2(acc[mt][nt][0], acc[mt][nt][1]);
            float2 v1 = make_float2(acc[mt][nt][2], acc[mt][nt][3]);
            if (MODE >= 1) {
                float c0 = bs[col], c1 = bs[col + 1];
                v0.x = fmaxf(v0.x + c0, 0.f); v0.y = fmaxf(v0.y + c1, 0.f);
                v1.x = fmaxf(v1.x + c0, 0.f); v1.y = fmaxf(v1.y + c1, 0.f);
            }
            if (MODE == 2) {
                if (b0i >= 0) {
                    float* p = gsum + b0i * MOUT + col;
                    asm volatile("red.global.add.v2.f32 [%0], {%1,%2};"
                                 :: "l"(p), "f"(v0.x), "f"(v0.y) : "memory");
                }
                if (b1i >= 0) {
                    float* p = gsum + b1i * MOUT + col;
                    asm volatile("red.global.add.v2.f32 [%0], {%1,%2};"
                                 :: "l"(p), "f"(v1.x), "f"(v1.y) : "memory");
                }
            } else {
                if (row < N)     *(float2*)(Y + (long)row * MOUT + col)       = v0;
                if (row + 8 < N) *(float2*)(Y + (long)(row + 8) * MOUT + col) = v1;
            }
        }
    }
}

// ================= token gather + mean pool =================
__global__ void embed_pool_kernel(const int* __restrict__ tokens,
                                  const float* __restrict__ embWp,
                                  const float* __restrict__ bp,
                                  float* __restrict__ node, int N) {
    int warp = (blockIdx.x * blockDim.x + threadIdx.x) >> 5;
    int lane = threadIdx.x & 31;
    if (warp >= N) return;
    const int* tp = tokens + warp * N_TOKENS;
    float2 acc = make_float2(0.f, 0.f);
#pragma unroll
    for (int t = 0; t < N_TOKENS; t++) {
        int tok = tp[t];
        float2 v = ((const float2*)embWp)[tok * (NODE_DIM / 2) + lane];
        acc.x += v.x; acc.y += v.y;
    }
    float2 b = ((const float2*)bp)[lane];
    float2 o = make_float2(acc.x * (1.0f / N_TOKENS) + b.x,
                           acc.y * (1.0f / N_TOKENS) + b.y);
    ((float2*)node)[warp * (NODE_DIM / 2) + lane] = o;
}

// ================= CSR build =================
__global__ void hist_kernel(const int* __restrict__ dst, int* __restrict__ ctr, int E) {
    int e = blockIdx.x * blockDim.x + threadIdx.x;
    if (e < E) atomicAdd(ctr + dst[e], 1);
}
__global__ void scan_kernel(const int* __restrict__ deg, int* __restrict__ row_ptr,
                            float* __restrict__ dis, int N) {
    __shared__ int ssum[1024];
    int t = threadIdx.x;
    int chunk = (N + 1023) / 1024;
    int lo = t * chunk;
    int hi = lo + chunk; if (hi > N) hi = N; if (lo > N) lo = N;
    int s = 0;
    for (int i = lo; i < hi; i++) s += deg[i];
    ssum[t] = s;
    __syncthreads();
    for (int off = 1; off < 1024; off <<= 1) {
        int v = (t >= off) ? ssum[t - off] : 0;
        __syncthreads();
        ssum[t] += v;
        __syncthreads();
    }
    int prefix = (t == 0) ? 0 : ssum[t - 1];
    for (int i = lo; i < hi; i++) {
        int d = deg[i];
        row_ptr[i] = prefix;
        dis[i] = rsqrtf((float)(d + 1));
        prefix += d;
    }
    if (t == 1023) row_ptr[N] = prefix;
}
__global__ void scatter_kernel(const int* __restrict__ src, const int* __restrict__ dst,
                               const int* __restrict__ row_ptr, const float* __restrict__ dis,
                               int* __restrict__ ctr, uint2* __restrict__ csr, int E) {
    int e = blockIdx.x * blockDim.x + threadIdx.x;
    if (e >= E) return;
    int s = __ldg(src + e), d = __ldg(dst + e);
    int off = atomicAdd(ctr + d, 1);
    float w = __ldg(dis + s) * __ldg(dis + d);
    csr[__ldg(row_ptr + d) + off] = make_uint2((unsigned)s, __float_as_uint(w));
}
__global__ void batch_count_kernel(const int* __restrict__ batch, float* __restrict__ gcnt, int N) {
    int i = blockIdx.x * blockDim.x + threadIdx.x;
    if (i < N) atomicAdd(gcnt + batch[i], 1.0f);
}

// ================= CSR aggregation (2-way edge pairing for MLP) =================
__global__ void agg64_kernel(const int* __restrict__ row_ptr, const uint2* __restrict__ csr,
                             const float* __restrict__ dis, const float* __restrict__ xin,
                             float* __restrict__ xout, int N) {
    int node = (blockIdx.x * blockDim.x + threadIdx.x) >> 5;
    int lane = threadIdx.x & 31;
    if (node >= N) return;
    int beg = __ldg(row_ptr + node), end = __ldg(row_ptr + node + 1);
    float di = __ldg(dis + node);
    float w0 = di * di;
    float2 v = ((const float2*)xin)[node * 32 + lane];
    float2 acc = make_float2(v.x * w0, v.y * w0);
    int j = beg;
    for (; j + 1 < end; j += 2) {
        uint2 e0 = __ldg(csr + j);
        uint2 e1 = __ldg(csr + j + 1);
        float2 u0 = ((const float2*)xin)[(int)e0.x * 32 + lane];
        float2 u1 = ((const float2*)xin)[(int)e1.x * 32 + lane];
        float wa = __uint_as_float(e0.y), wb = __uint_as_float(e1.y);
        acc.x += u0.x * wa + u1.x * wb;
        acc.y += u0.y * wa + u1.y * wb;
    }
    if (j < end) {
        uint2 e0 = __ldg(csr + j);
        float2 u0 = ((const float2*)xin)[(int)e0.x * 32 + lane];
        float wa = __uint_as_float(e0.y);
        acc.x += u0.x * wa; acc.y += u0.y * wa;
    }
    ((float2*)xout)[node * 32 + lane] = acc;
}
__global__ void agg128_kernel(const int* __restrict__ row_ptr, const uint2* __restrict__ csr,
                              const float* __restrict__ dis, const float* __restrict__ xin,
                              float* __restrict__ xout, int N) {
    int node = (blockIdx.x * blockDim.x + threadIdx.x) >> 5;
    int lane = threadIdx.x & 31;
    if (node >= N) return;
    int beg = __ldg(row_ptr + node), end = __ldg(row_ptr + node + 1);
    float di = __ldg(dis + node);
    float w0 = di * di;
    float4 v = ((const float4*)xin)[node * 32 + lane];
    float4 acc = make_float4(v.x * w0, v.y * w0, v.z * w0, v.w * w0);
    int j = beg;
    for (; j + 1 < end; j += 2) {
        uint2 e0 = __ldg(csr + j);
        uint2 e1 = __ldg(csr + j + 1);
        float4 u0 = ((const float4*)xin)[(int)e0.x * 32 + lane];
        float4 u1 = ((const float4*)xin)[(int)e1.x * 32 + lane];
        float wa = __uint_as_float(e0.y), wb = __uint_as_float(e1.y);
        acc.x += u0.x * wa + u1.x * wb;
        acc.y += u0.y * wa + u1.y * wb;
        acc.z += u0.z * wa + u1.z * wb;
        acc.w += u0.w * wa + u1.w * wb;
    }
    if (j < end) {
        uint2 e0 = __ldg(csr + j);
        float4 u0 = ((const float4*)xin)[(int)e0.x * 32 + lane];
        float wa = __uint_as_float(e0.y);
        acc.x += u0.x * wa; acc.y += u0.y * wa; acc.z += u0.z * wa; acc.w += u0.w * wa;
    }
    ((float4*)xout)[node * 32 + lane] = acc;
}

// ================= head =================
__global__ void head_kernel(const float* __restrict__ Wfc, const float* __restrict__ bfc,
                            const float* __restrict__ Wout, const float* __restrict__ bout,
                            float* __restrict__ out, int out_size) {
    __shared__ float gsh[HID];
    __shared__ float red[HID];
    int gid = blockIdx.x;
    int j   = threadIdx.x;
    float cnt = fmaxf(g_gcnt[gid], 1.0f);
    gsh[j] = g_gsum[gid * HID + j] / cnt;
    __syncthreads();
    float acc = bfc[j];
#pragma unroll 8
    for (int k = 0; k < HID; k++) acc += gsh[k] * Wfc[k * HID + j];
    acc = fmaxf(acc, 0.f);
    red[j] = acc * Wout[j];
    __syncthreads();
#pragma unroll
    for (int s = HID / 2; s > 0; s >>= 1) {
        if (j < s) red[j] += red[j + s];
        __syncthreads();
    }
    if (j == 0) {
        float logit = red[0] + bout[0];
        out[gid] = 1.0f / (1.0f + expf(-logit));
        if (out_size >= 2 * NG) out[NG + gid] = logit;
    }
}

// ================= launch =================
extern "C" void kernel_launch(void* const* d_in, const int* in_sizes, int n_in,
                              void* d_out, int out_size) {
    const int*   tokens = (const int*)  d_in[0];
    const int*   eidx   = (const int*)  d_in[1];
    const int*   batch  = (const int*)  d_in[2];
    const float* emb    = (const float*)d_in[3];
    const float* Wp     = (const float*)d_in[4];
    const float* bp     = (const float*)d_in[5];
    const float* W1     = (const float*)d_in[6];
    const float* b1     = (const float*)d_in[7];
    const float* W2     = (const float*)d_in[8];
    const float* b2     = (const float*)d_in[9];
    const float* Wfc    = (const float*)d_in[10];
    const float* bfc    = (const float*)d_in[11];
    const float* Wout   = (const float*)d_in[12];
    const float* bout   = (const float*)d_in[13];
    float* out = (float*)d_out;

    const int N = in_sizes[2];
    const int E = in_sizes[1] / 2;
    const int* src = eidx;
    const int* dst = eidx + E;

    float *embWp, *node, *tmp, *x, *dis, *gsum, *gcnt;
    int *ctr, *rowptr; uint2 *csr;
    __nv_bfloat16 *wpth, *wptl, *wt1h, *wt1l, *wt2h, *wt2l;
    cudaGetSymbolAddress((void**)&embWp,  g_embWp);
    cudaGetSymbolAddress((void**)&node,   g_node);
    cudaGetSymbolAddress((void**)&tmp,    g_tmp);
    cudaGetSymbolAddress((void**)&x,      g_x);
    cudaGetSymbolAddress((void**)&dis,    g_dis);
    cudaGetSymbolAddress((void**)&ctr,    g_ctr);
    cudaGetSymbolAddress((void**)&rowptr, g_rowptr);
    cudaGetSymbolAddress((void**)&csr,    g_csr);
    cudaGetSymbolAddress((void**)&gsum,   g_gsum);
    cudaGetSymbolAddress((void**)&gcnt,   g_gcnt);
    cudaGetSymbolAddress((void**)&wpth,   g_wpth);
    cudaGetSymbolAddress((void**)&wptl,   g_wptl);
    cudaGetSymbolAddress((void**)&wt1h,   g_wt1h);
    cudaGetSymbolAddress((void**)&wt1l,   g_wt1l);
    cudaGetSymbolAddress((void**)&wt2h,   g_wt2h);
    cudaGetSymbolAddress((void**)&wt2l,   g_wt2l);

    // one-time host resources for graph-parallel branches
    static cudaStream_t s2 = nullptr;
    static cudaEvent_t evFork = nullptr, evJoin = nullptr;
    if (s2 == nullptr) {
        cudaStreamCreateWithFlags(&s2, cudaStreamNonBlocking);
        cudaEventCreateWithFlags(&evFork, cudaEventDisableTiming);
        cudaEventCreateWithFlags(&evJoin, cudaEventDisableTiming);
    }

    const int SMEM_V  = 512 + 256 * 144 + 2 * 64  * 144;   //  55808 (K=64,  M=64)
    const int SMEM_L1 = 512 + 256 * 144 + 2 * 128 * 144;   //  74240 (K=64,  M=128)
    const int SMEM_L2 = 512 + 256 * 272 + 2 * 128 * 272;   // 139776 (K=128, M=128)
    cudaFuncSetAttribute(mma_gemm_kernel<64, 64, 0>,   cudaFuncAttributeMaxDynamicSharedMemorySize, SMEM_V);
    cudaFuncSetAttribute(mma_gemm_kernel<64, 128, 1>,  cudaFuncAttributeMaxDynamicSharedMemorySize, SMEM_L1);
    cudaFuncSetAttribute(mma_gemm_kernel<128, 128, 2>, cudaFuncAttributeMaxDynamicSharedMemorySize, SMEM_L2);

    // ---- fork: CSR build + pooling prep on s2, embedding path on main ----
    cudaEventRecord(evFork, 0);
    cudaStreamWaitEvent(s2, evFork, 0);

    // s2 branch: CSR build (independent of features) + gcnt/gsum prep
    cudaMemsetAsync(ctr, 0, N * sizeof(int), s2);
    cudaMemsetAsync(gsum, 0, NG * HID * sizeof(float), s2);
    cudaMemsetAsync(gcnt, 0, NG * sizeof(float), s2);
    hist_kernel<<<(E + 255) / 256, 256, 0, s2>>>(dst, ctr, E);
    batch_count_kernel<<<(N + 255) / 256, 256, 0, s2>>>(batch, gcnt, N);
    scan_kernel<<<1, 1024, 0, s2>>>(ctr, rowptr, dis, N);
    cudaMemsetAsync(ctr, 0, N * sizeof(int), s2);
    scatter_kernel<<<(E + 255) / 256, 256, 0, s2>>>(src, dst, rowptr, dis, ctr, csr, E);
    cudaEventRecord(evJoin, s2);

    // main branch: weight split + vocab projection + token pooling
    convert_w_kernel<TOK_DIM, NODE_DIM><<<(NODE_DIM * TOK_DIM + 255) / 256, 256>>>(Wp, wpth, wptl);
    convert_w_kernel<NODE_DIM, HID><<<(HID * NODE_DIM + 255) / 256, 256>>>(W1, wt1h, wt1l);
    convert_w_kernel<HID, HID><<<(HID * HID + 255) / 256, 256>>>(W2, wt2h, wt2l);
    mma_gemm_kernel<64, 64, 0><<<(VOCAB + 127) / 128, 256, SMEM_V>>>(
        emb, wpth, wptl, nullptr, embWp, nullptr, nullptr, VOCAB);
    embed_pool_kernel<<<(N * 32 + 255) / 256, 256>>>(tokens, embWp, bp, node, N);

    // join: aggregation needs both CSR and node features
    cudaStreamWaitEvent(0, evJoin, 0);

    // ---- GCN layer 1: aggregate(64) -> tensor GEMM 64->128 + bias + relu ----
    agg64_kernel<<<(N * 32 + 255) / 256, 256>>>(rowptr, csr, dis, node, tmp, N);
    mma_gemm_kernel<64, 128, 1><<<(N + 127) / 128, 256, SMEM_L1>>>(
        tmp, wt1h, wt1l, b1, x, nullptr, nullptr, N);

    // ---- GCN layer 2: aggregate(128) -> tensor GEMM + bias + relu + fused pooling ----
    agg128_kernel<<<(N * 32 + 255) / 256, 256>>>(rowptr, csr, dis, x, tmp, N);
    mma_gemm_kernel<128, 128, 2><<<(N + 127) / 128, 256, SMEM_L2>>>(
        tmp, wt2h, wt2l, b2, nullptr, batch, gsum, N);

    // ---- head ----
    head_kernel<<<NG, HID>>>(Wfc, bfc, Wout, bout, out, out_size);
}